// round 3
// baseline (speedup 1.0000x reference)
#include <cuda_runtime.h>
#include <math.h>

// Problem dims
#define T_STEPS 8
#define N_PED   2048
#define H_DIM   128
#define D_IN    64
#define G4H     512   // 4*H
#define N_GRP   64
#define GRP_N   32
#define DD_DIM  64
#define NH      4

typedef unsigned long long ull;

// packed f32x2 helpers (sm_100+)
#define FMA2(d, a, b, c) asm("fma.rn.f32x2 %0, %1, %2, %3;" : "=l"(d) : "l"(a), "l"(b), "l"(c))
#define PK2(dst, s) do { unsigned _u = __float_as_uint(s); \
    asm("mov.b64 %0, {%1, %1};" : "=l"(dst) : "r"(_u)); } while (0)
#define PKAB(dst, a, b) do { unsigned _ua = __float_as_uint(a), _ub = __float_as_uint(b); \
    asm("mov.b64 %0, {%1, %2};" : "=l"(dst) : "r"(_ua), "r"(_ub)); } while (0)
#define UNPK2(lo, hi, v) do { unsigned _a, _b; \
    asm("mov.b64 {%0, %1}, %2;" : "=r"(_a), "=r"(_b) : "l"(v)); \
    lo = __uint_as_float(_a); hi = __uint_as_float(_b); } while (0)

// ---------------- scratch (device globals; no allocation) ----------------
__device__ __align__(16) float d_x  [T_STEPS * N_PED * D_IN];  // embedded input
__device__ __align__(16) float d_wt [H_DIM * G4H];             // W_hh^T, k-major [128][512]
__device__ __align__(16) float d_wit[D_IN * G4H];              // W_ih^T, k-major [64][512]
__device__ __align__(16) float d_bsum[G4H];                    // b_ih + b_hh
__device__ __align__(16) float d_h [N_PED * H_DIM];
__device__ __align__(16) float d_th[N_PED * H_DIM];            // tanh(h)
__device__ __align__(16) float d_uv[2 * NH * H_DIM];           // u then v
__device__ __align__(16) float d_m [NH * N_PED * H_DIM];       // attention-pooled features

// ---------------- fast activations ----------------
__device__ __forceinline__ float sigf(float x) {
    return __fdividef(1.f, 1.f + __expf(-x));
}
__device__ __forceinline__ float tanh_f(float x) {
    // 1 - 2/(e^{2x}+1): no NaN at either infinity
    return 1.f - __fdividef(2.f, __expf(2.f * x) + 1.f);
}

// ---------------- embedding: x = relu(obs @ W_emb + b_emb) ----------------
__global__ void embed_kernel(const float* __restrict__ obs,
                             const float* __restrict__ W_emb,
                             const float* __restrict__ b_emb)
{
    int idx = blockIdx.x * blockDim.x + threadIdx.x;   // < T*N*64
    int row = idx >> 6;
    int c   = idx & 63;
    float o0 = obs[row * 2 + 0];
    float o1 = obs[row * 2 + 1];
    float v  = fmaf(o0, W_emb[c], fmaf(o1, W_emb[64 + c], b_emb[c]));
    d_x[idx] = fmaxf(v, 0.f);
}

// ---------------- weight prep: transpose to k-major + bias sum ----------------
__global__ void prep_kernel(const float* __restrict__ W_hh, const float* __restrict__ W_ih,
                            const float* __restrict__ b_ih, const float* __restrict__ b_hh)
{
    int i = blockIdx.x * 256 + threadIdx.x;
    if (i < H_DIM * G4H) {
        d_wt[i] = W_hh[(i % G4H) * H_DIM + (i / G4H)];
        return;
    }
    int j = i - H_DIM * G4H;
    if (j < D_IN * G4H) {
        d_wit[j] = W_ih[(j % G4H) * D_IN + (j / G4H)];
        return;
    }
    int b = j - D_IN * G4H;
    if (b < G4H) d_bsum[b] = b_ih[b] + b_hh[b];
}

// ---------------- fully fused LSTM: 8 steps, warp-synchronous ----------------
// grid = 128 blocks (16 peds each), 256 threads (8 warps, 2 peds/warp).
// Gate n-index for a lane: n = u*128 + 4*lane + v  ->  u selects i/f/g/o,
// channel = 4*lane + v, so the epilogue is lane-local (no data exchange).
__global__ __launch_bounds__(256) void lstm_fused(const float* __restrict__ h0,
                                                  const float* __restrict__ c0)
{
    __shared__ __align__(16) float h_sh[16][H_DIM];
    __shared__ __align__(16) float x_sh[T_STEPS][16][D_IN];
    int tid = threadIdx.x, w = tid >> 5, lane = tid & 31;
    int p0 = blockIdx.x * 16;

    // stage h0
    {
        float4* dst = (float4*)&h_sh[0][0];
        const float4* src = (const float4*)&h0[(size_t)p0 * H_DIM];
        for (int i = tid; i < 512; i += 256) dst[i] = src[i];
    }
    // stage x (all 8 timesteps for this block's peds)
    {
        float4* dst = (float4*)&x_sh[0][0][0];
        for (int i = tid; i < 2048; i += 256) {
            int t = i >> 8;          // 256 float4 per timestep (16 peds * 16)
            int r = i & 255;
            dst[i] = *(const float4*)&d_x[((size_t)(t * N_PED) + p0 + (r >> 4)) * D_IN + ((r & 15) << 2)];
        }
    }
    int pa = 2 * w, pb = 2 * w + 1;
    // c in registers
    float c_reg[2][4];
    {
        float4 ca = *(const float4*)&c0[(size_t)(p0 + pa) * H_DIM + 4 * lane];
        float4 cb = *(const float4*)&c0[(size_t)(p0 + pb) * H_DIM + 4 * lane];
        c_reg[0][0] = ca.x; c_reg[0][1] = ca.y; c_reg[0][2] = ca.z; c_reg[0][3] = ca.w;
        c_reg[1][0] = cb.x; c_reg[1][1] = cb.y; c_reg[1][2] = cb.z; c_reg[1][3] = cb.w;
    }
    // packed bias init values
    ull binit[4][2];
#pragma unroll
    for (int u = 0; u < 4; u++) {
        binit[u][0] = *(const ull*)&d_bsum[u * 128 + 4 * lane];
        binit[u][1] = *(const ull*)&d_bsum[u * 128 + 4 * lane + 2];
    }
    __syncthreads();

    const ulonglong2* wt2  = (const ulonglong2*)d_wt;   // [128][128] ull2 per row
    const ulonglong2* wit2 = (const ulonglong2*)d_wit;  // [64][128]

    for (int t = 0; t < T_STEPS; t++) {
        ull acc[2][4][2];
#pragma unroll
        for (int u = 0; u < 4; u++) {
            acc[0][u][0] = binit[u][0]; acc[0][u][1] = binit[u][1];
            acc[1][u][0] = binit[u][0]; acc[1][u][1] = binit[u][1];
        }
        // recurrent part: K = 128
#pragma unroll 4
        for (int k = 0; k < H_DIM; k++) {
            ull ha, hb;
            PK2(ha, h_sh[pa][k]);
            PK2(hb, h_sh[pb][k]);
#pragma unroll
            for (int u = 0; u < 4; u++) {
                ulonglong2 wv = wt2[k * 128 + u * 32 + lane];
                FMA2(acc[0][u][0], ha, wv.x, acc[0][u][0]);
                FMA2(acc[0][u][1], ha, wv.y, acc[0][u][1]);
                FMA2(acc[1][u][0], hb, wv.x, acc[1][u][0]);
                FMA2(acc[1][u][1], hb, wv.y, acc[1][u][1]);
            }
        }
        // input part: K = 64
#pragma unroll 4
        for (int k = 0; k < D_IN; k++) {
            ull xa, xb;
            PK2(xa, x_sh[t][pa][k]);
            PK2(xb, x_sh[t][pb][k]);
#pragma unroll
            for (int u = 0; u < 4; u++) {
                ulonglong2 wv = wit2[k * 128 + u * 32 + lane];
                FMA2(acc[0][u][0], xa, wv.x, acc[0][u][0]);
                FMA2(acc[0][u][1], xa, wv.y, acc[0][u][1]);
                FMA2(acc[1][u][0], xb, wv.x, acc[1][u][0]);
                FMA2(acc[1][u][1], xb, wv.y, acc[1][u][1]);
            }
        }
        // epilogue: lane-local activations, update c (regs) and h (smem)
#pragma unroll
        for (int pp = 0; pp < 2; pp++) {
            int p = 2 * w + pp;
#pragma unroll
            for (int x2 = 0; x2 < 2; x2++) {
                float i0, i1, f0, f1, g0, g1, o0, o1;
                UNPK2(i0, i1, acc[pp][0][x2]);
                UNPK2(f0, f1, acc[pp][1][x2]);
                UNPK2(g0, g1, acc[pp][2][x2]);
                UNPK2(o0, o1, acc[pp][3][x2]);
                int ch = 4 * lane + 2 * x2;
                float cn0 = sigf(f0) * c_reg[pp][2 * x2]     + sigf(i0) * tanh_f(g0);
                float cn1 = sigf(f1) * c_reg[pp][2 * x2 + 1] + sigf(i1) * tanh_f(g1);
                c_reg[pp][2 * x2]     = cn0;
                c_reg[pp][2 * x2 + 1] = cn1;
                h_sh[p][ch]     = sigf(o0) * tanh_f(cn0);
                h_sh[p][ch + 1] = sigf(o1) * tanh_f(cn1);
            }
        }
        __syncwarp();
    }
    __syncthreads();
    // write h and tanh(h)
    for (int i = tid; i < 16 * H_DIM; i += 256) {
        float v = h_sh[i >> 7][i & 127];
        d_h [(size_t)p0 * H_DIM + i] = v;
        d_th[(size_t)p0 * H_DIM + i] = tanh_f(v);
    }
}

// ---------------- u_h = w_h @ a1, v_h = w_h @ a2 ----------------
__global__ void uv_kernel(const float* __restrict__ gat_w,
                          const float* __restrict__ gat_a)
{
    int h = blockIdx.x;
    int tid = threadIdx.x;            // 0..255
    int c = tid & 127;
    const float* a = gat_a + ((tid < 128) ? 0 : 128);
    const float* w = gat_w + (size_t)h * H_DIM * H_DIM + (size_t)c * H_DIM;
    float s = 0.f;
#pragma unroll 8
    for (int o = 0; o < 128; o++) s = fmaf(w[o], a[o], s);
    d_uv[((tid < 128) ? h : NH + h) * H_DIM + c] = s;
}

// ---------------- GAT main: per (group, row i), 128 threads ----------------
__global__ __launch_bounds__(128) void gat_kernel(
    const float* __restrict__ goal_hidden, const float* __restrict__ goal,
    const float* __restrict__ action,      const float* __restrict__ W_dist,
    const float* __restrict__ b_dist,      const float* __restrict__ W_gate,
    const float* __restrict__ b_gate)
{
    int i = blockIdx.x;       // row within group
    int g = blockIdx.y;       // group
    int tid = threadIdx.x;    // 0..127
    int p = g * GRP_N + i;

    __shared__ __align__(16) float th_sh[GRP_N][H_DIM];     // tanh(ah[j]) (precomputed)
    __shared__ __align__(16) float gate_sh[GRP_N][H_DIM];
    __shared__ __align__(16) float r_sh[GRP_N][DD_DIM];
    __shared__ float ahv[H_DIM], ghv[H_DIM];
    __shared__ float pax[GRP_N], pay[GRP_N], pgx[GRP_N], pgy[GRP_N];
    __shared__ float sdot_sh[NH][GRP_N];
    __shared__ float scr[NH][GRP_N + 1];
    __shared__ float alpha_sh[NH][GRP_N + 1];
    __shared__ float hsum[NH][3];             // su, sv, sg

    // P0: loads (tanh hoisted to d_th)
    ahv[tid] = d_h[(size_t)p * H_DIM + tid];
    ghv[tid] = goal_hidden[(size_t)p * H_DIM + tid];
    if (tid < GRP_N) {
        int q = g * GRP_N + tid;
        pax[tid] = action[q * 2 + 0]; pay[tid] = action[q * 2 + 1];
        pgx[tid] = goal[q * 2 + 0];   pgy[tid] = goal[q * 2 + 1];
    }
    for (int j = 0; j < GRP_N; j++)
        th_sh[j][tid] = d_th[(size_t)(g * GRP_N + j) * H_DIM + tid];
    __syncthreads();

    // P1: r[j][d] = relu(dist(i,j) @ W_dist + b_dist)
    {
        float aix = pax[i], aiy = pay[i], gix = pgx[i], giy = pgy[i];
        for (int it = 0; it < 16; it++) {
            int idx = tid + 128 * it;
            int j = idx >> 6, d = idx & 63;
            float acc = b_dist[d];
            acc = fmaf(aix, W_dist[0 * 64 + d], acc);
            acc = fmaf(aiy, W_dist[1 * 64 + d], acc);
            acc = fmaf(gix, W_dist[2 * 64 + d], acc);
            acc = fmaf(giy, W_dist[3 * 64 + d], acc);
            acc = fmaf(pax[j], W_dist[4 * 64 + d], acc);
            acc = fmaf(pay[j], W_dist[5 * 64 + d], acc);
            acc = fmaf(pgx[j], W_dist[6 * 64 + d], acc);
            acc = fmaf(pgy[j], W_dist[7 * 64 + d], acc);
            r_sh[j][d] = fmaxf(acc, 0.f);
        }
    }
    __syncthreads();

    // P2: gate[j][c=tid] = sigmoid(r[j] @ W_gate[:,c] + b_gate[c])  — packed f32x2
    {
        ull acc2[GRP_N];
#pragma unroll
        for (int j = 0; j < GRP_N; j++) acc2[j] = 0ull;
        for (int d0 = 0; d0 < DD_DIM; d0 += 4) {
            float w0 = W_gate[(d0 + 0) * H_DIM + tid];
            float w1 = W_gate[(d0 + 1) * H_DIM + tid];
            float w2 = W_gate[(d0 + 2) * H_DIM + tid];
            float w3 = W_gate[(d0 + 3) * H_DIM + tid];
            ull ww0, ww1;
            PKAB(ww0, w0, w1);
            PKAB(ww1, w2, w3);
#pragma unroll
            for (int j = 0; j < GRP_N; j++) {
                ulonglong2 rv = *(const ulonglong2*)&r_sh[j][d0];
                FMA2(acc2[j], rv.x, ww0, acc2[j]);
                FMA2(acc2[j], rv.y, ww1, acc2[j]);
            }
        }
        float bg = b_gate[tid];
#pragma unroll
        for (int j = 0; j < GRP_N; j++) {
            float lo, hi;
            UNPK2(lo, hi, acc2[j]);
            gate_sh[j][tid] = sigf(lo + hi + bg);
        }
    }
    __syncthreads();

    // P3: per-head dots. warp h handles head h.
    {
        int wid = tid >> 5, lane = tid & 31;
        const float* uh = d_uv + wid * H_DIM;
        const float* vh = d_uv + (NH + wid) * H_DIM;
        for (int j = 0; j < GRP_N; j++) {
            float s = 0.f;
#pragma unroll
            for (int cc = lane; cc < H_DIM; cc += 32)
                s = fmaf(gate_sh[j][cc] * th_sh[j][cc], vh[cc], s);
#pragma unroll
            for (int o = 16; o; o >>= 1) s += __shfl_xor_sync(0xffffffffu, s, o);
            if (lane == 0) sdot_sh[wid][j] = s;
        }
        float su = 0.f, sv = 0.f, sg = 0.f;
#pragma unroll
        for (int cc = lane; cc < H_DIM; cc += 32) {
            su = fmaf(ahv[cc], uh[cc], su);
            sv = fmaf(ahv[cc], vh[cc], sv);
            sg = fmaf(ghv[cc], vh[cc], sg);
        }
#pragma unroll
        for (int o = 16; o; o >>= 1) {
            su += __shfl_xor_sync(0xffffffffu, su, o);
            sv += __shfl_xor_sync(0xffffffffu, sv, o);
            sg += __shfl_xor_sync(0xffffffffu, sg, o);
        }
        if (lane == 0) { hsum[wid][0] = su; hsum[wid][1] = sv; hsum[wid][2] = sg; }
    }
    __syncthreads();

    // P4: scores (leaky relu) + softmax over k=0..32 per head
    for (int idx = tid; idx < NH * (GRP_N + 1); idx += 128) {
        int h = idx / (GRP_N + 1), k = idx % (GRP_N + 1);
        float s;
        if (k == 0) s = hsum[h][0] + hsum[h][1];
        else {
            int j = k - 1;
            s = hsum[h][0] + ((j == i) ? hsum[h][2] : sdot_sh[h][j]);
        }
        scr[h][k] = (s >= 0.f) ? s : 0.2f * s;
    }
    __syncthreads();
    if (tid < NH) {
        int h = tid;
        float mx = -1e30f;
        for (int k = 0; k <= GRP_N; k++) mx = fmaxf(mx, scr[h][k]);
        float sum = 0.f;
        for (int k = 0; k <= GRP_N; k++) sum += expf(scr[h][k] - mx);
        float inv = 1.f / sum;
        for (int k = 0; k <= GRP_N; k++) alpha_sh[h][k] = expf(scr[h][k] - mx) * inv;
    }
    __syncthreads();

    // P5: m[h][c] = alpha0*ah[c] + sum_j alpha_{j+1} * goal_action[j][c]
    {
        int c = tid;
        float ahc = ahv[c], ghc = ghv[c];
        for (int h = 0; h < NH; h++) {
            float mv = alpha_sh[h][0] * ahc;
#pragma unroll 8
            for (int j = 0; j < GRP_N; j++) {
                float ga = (j == i) ? ghc : gate_sh[j][c] * th_sh[j][c];
                mv = fmaf(alpha_sh[h][j + 1], ga, mv);
            }
            d_m[((size_t)h * N_PED + p) * H_DIM + c] = mv;
        }
    }
}

// ---------------- final: out = relu(0.25 * sum_h m_h @ w_h) + gat_bias ----------------
__global__ __launch_bounds__(128) void g3_kernel(
    const float* __restrict__ gat_w, const float* __restrict__ gat_bias,
    float* __restrict__ out)
{
    const int TP = 8;
    int p0 = blockIdx.x * TP;
    int tid = threadIdx.x;   // output column c
    __shared__ __align__(16) float m_sh[TP][H_DIM];
    float acc[TP];
#pragma unroll
    for (int r = 0; r < TP; r++) acc[r] = 0.f;

    for (int h = 0; h < NH; h++) {
        __syncthreads();
#pragma unroll
        for (int r = 0; r < TP; r++)
            m_sh[r][tid] = d_m[((size_t)h * N_PED + p0 + r) * H_DIM + tid];
        __syncthreads();
        const float* wh = gat_w + (size_t)h * H_DIM * H_DIM;
        for (int f0 = 0; f0 < H_DIM; f0 += 8) {
            float w[8];
#pragma unroll
            for (int dd = 0; dd < 8; dd++) w[dd] = wh[(f0 + dd) * H_DIM + tid];
#pragma unroll
            for (int r = 0; r < TP; r++) {
#pragma unroll
                for (int dd = 0; dd < 8; dd++)
                    acc[r] = fmaf(m_sh[r][f0 + dd], w[dd], acc[r]);
            }
        }
    }
    float b = gat_bias[tid];
#pragma unroll
    for (int r = 0; r < TP; r++)
        out[(size_t)(p0 + r) * H_DIM + tid] = fmaxf(0.25f * acc[r], 0.f) + b;
}

// ---------------- host ----------------
extern "C" void kernel_launch(void* const* d_in, const int* in_sizes, int n_in,
                              void* d_out, int out_size)
{
    const float* obs         = (const float*)d_in[0];
    const float* goal_hidden = (const float*)d_in[1];
    const float* goal        = (const float*)d_in[2];
    const float* action      = (const float*)d_in[3];
    const float* h0          = (const float*)d_in[4];
    const float* c0          = (const float*)d_in[5];
    const float* W_emb       = (const float*)d_in[6];
    const float* b_emb       = (const float*)d_in[7];
    const float* W_ih        = (const float*)d_in[8];
    const float* W_hh        = (const float*)d_in[9];
    const float* b_ih        = (const float*)d_in[10];
    const float* b_hh        = (const float*)d_in[11];
    const float* W_dist      = (const float*)d_in[12];
    const float* b_dist      = (const float*)d_in[13];
    const float* W_gate      = (const float*)d_in[14];
    const float* b_gate      = (const float*)d_in[15];
    const float* gat_w       = (const float*)d_in[16];
    const float* gat_a       = (const float*)d_in[17];
    const float* gat_bias    = (const float*)d_in[18];
    float* out = (float*)d_out;

    // embedding + weight prep (independent)
    embed_kernel<<<(T_STEPS * N_PED * D_IN) / 256, 256>>>(obs, W_emb, b_emb);
    {
        int total = H_DIM * G4H + D_IN * G4H + G4H;
        prep_kernel<<<(total + 255) / 256, 256>>>(W_hh, W_ih, b_ih, b_hh);
    }

    // fused 8-step LSTM (writes d_h and d_th)
    lstm_fused<<<N_PED / 16, 256>>>(h0, c0);

    // GAT
    uv_kernel<<<NH, 256>>>(gat_w, gat_a);
    gat_kernel<<<dim3(GRP_N, N_GRP), 128>>>(goal_hidden, goal, action,
                                            W_dist, b_dist, W_gate, b_gate);
    g3_kernel<<<N_PED / 8, 128>>>(gat_w, gat_bias, out);
}

// round 4
// speedup vs baseline: 1.0627x; 1.0627x over previous
#include <cuda_runtime.h>
#include <math.h>

// Problem dims
#define T_STEPS 8
#define N_PED   2048
#define H_DIM   128
#define D_IN    64
#define G4H     512   // 4*H
#define N_GRP   64
#define GRP_N   32
#define DD_DIM  64
#define NH      4

typedef unsigned long long ull;

// packed f32x2 helpers (sm_100+)
#define FMA2(d, a, b, c) asm("fma.rn.f32x2 %0, %1, %2, %3;" : "=l"(d) : "l"(a), "l"(b), "l"(c))
#define PK2(dst, s) do { unsigned _u = __float_as_uint(s); \
    asm("mov.b64 %0, {%1, %1};" : "=l"(dst) : "r"(_u)); } while (0)
#define PKAB(dst, a, b) do { unsigned _ua = __float_as_uint(a), _ub = __float_as_uint(b); \
    asm("mov.b64 %0, {%1, %2};" : "=l"(dst) : "r"(_ua), "r"(_ub)); } while (0)
#define UNPK2(lo, hi, v) do { unsigned _a, _b; \
    asm("mov.b64 {%0, %1}, %2;" : "=r"(_a), "=r"(_b) : "l"(v)); \
    lo = __uint_as_float(_a); hi = __uint_as_float(_b); } while (0)

// ---------------- scratch (device globals; no allocation) ----------------
// Permuted weight layout: for k-row k, 512 floats ordered as
//   [half 0..1][tx 0..63][u 0..3]  where gate n = u*128 + 2*tx + half.
__device__ __align__(16) float d_wt  [H_DIM * G4H];   // W_hh permuted, [128][512]
__device__ __align__(16) float d_wit [D_IN * G4H];    // W_ih permuted, [64][512]
__device__ __align__(16) float d_bsum[G4H];           // (b_ih+b_hh) permuted
__device__ __align__(16) float d_h [N_PED * H_DIM];
__device__ __align__(16) float d_th[N_PED * H_DIM];   // tanh(h)
__device__ __align__(16) float d_uv[2 * NH * H_DIM];  // u then v
__device__ __align__(16) float d_m [NH * N_PED * H_DIM];

// ---------------- fast activations ----------------
__device__ __forceinline__ float sigf(float x) {
    return __fdividef(1.f, 1.f + __expf(-x));
}
__device__ __forceinline__ float tanh_f(float x) {
    return 1.f - __fdividef(2.f, __expf(2.f * x) + 1.f);
}

// ---------------- weight prep: permute + bias sum ----------------
__global__ void prep_kernel(const float* __restrict__ W_hh, const float* __restrict__ W_ih,
                            const float* __restrict__ b_ih, const float* __restrict__ b_hh)
{
    int i = blockIdx.x * 256 + threadIdx.x;
    if (i < H_DIM * G4H) {
        int k = i >> 9, q = i & 511;
        int half = q >> 8, tx = (q >> 2) & 63, u = q & 3;
        int n = u * 128 + 2 * tx + half;
        d_wt[i] = W_hh[n * H_DIM + k];
        return;
    }
    int j = i - H_DIM * G4H;
    if (j < D_IN * G4H) {
        int k = j >> 9, q = j & 511;
        int half = q >> 8, tx = (q >> 2) & 63, u = q & 3;
        int n = u * 128 + 2 * tx + half;
        d_wit[j] = W_ih[n * D_IN + k];
        return;
    }
    int b = j - D_IN * G4H;
    if (b < G4H) {
        int half = b >> 8, tx = (b >> 2) & 63, u = b & 3;
        int n = u * 128 + 2 * tx + half;
        d_bsum[b] = b_ih[n] + b_hh[n];
    }
}

// ---------------- fused LSTM: 8 steps, register-blocked ----------------
// 256 threads: tx = tid&63 owns channels {2tx, 2tx+1} (all 4 gate types),
// ty = tid>>6 owns peds {4ty..4ty+3}. Per k: 2 LDG.128 of permuted W serve
// 16 FMA2 (4 peds x 4 packed-gate pairs). Epilogue is thread-local.
__global__ __launch_bounds__(256) void lstm_fused(
    const float* __restrict__ h0, const float* __restrict__ c0,
    const float* __restrict__ obs,
    const float* __restrict__ W_emb, const float* __restrict__ b_emb)
{
    __shared__ __align__(16) float h_sh[16][H_DIM];
    __shared__ __align__(16) float x_sh[T_STEPS][16][D_IN];
    int tid = threadIdx.x;
    int tx = tid & 63, ty = tid >> 6;
    int p0 = blockIdx.x * 16;

    // embed x for this block's 16 peds, all 8 timesteps (fused; no d_x pass)
    for (int i = tid; i < T_STEPS * 16 * D_IN; i += 256) {
        int t = i >> 10;          // 16*64 = 1024 per timestep
        int r = (i >> 6) & 15;    // ped within block
        int c = i & 63;
        const float* op = obs + ((size_t)t * N_PED + p0 + r) * 2;
        float v = fmaf(op[0], W_emb[c], fmaf(op[1], W_emb[64 + c], b_emb[c]));
        x_sh[t][r][c] = fmaxf(v, 0.f);
    }
    // stage h0
    {
        float4* dst = (float4*)&h_sh[0][0];
        const float4* src = (const float4*)&h0[(size_t)p0 * H_DIM];
        for (int i = tid; i < 512; i += 256) dst[i] = src[i];
    }
    // c in registers: peds 4ty+p, channels 2tx, 2tx+1
    float c_reg[4][2];
#pragma unroll
    for (int p = 0; p < 4; p++) {
        float2 cv = *(const float2*)&c0[(size_t)(p0 + 4 * ty + p) * H_DIM + 2 * tx];
        c_reg[p][0] = cv.x; c_reg[p][1] = cv.y;
    }
    // permuted bias (init values for accumulators)
    ulonglong2 binit0 = *(const ulonglong2*)&d_bsum[tx * 4];
    ulonglong2 binit1 = *(const ulonglong2*)&d_bsum[256 + tx * 4];
    __syncthreads();

    const ulonglong2* wt2 = (const ulonglong2*)d_wt;   // idx (k*2+half)*64 + tx
    const ulonglong2* wi2 = (const ulonglong2*)d_wit;

    for (int t = 0; t < T_STEPS; t++) {
        ull acc[4][4];
#pragma unroll
        for (int p = 0; p < 4; p++) {
            acc[p][0] = binit0.x; acc[p][1] = binit0.y;
            acc[p][2] = binit1.x; acc[p][3] = binit1.y;
        }
        // recurrent: K = 128
#pragma unroll 4
        for (int k = 0; k < H_DIM; k++) {
            ulonglong2 wa = wt2[(k * 2 + 0) * 64 + tx];
            ulonglong2 wb = wt2[(k * 2 + 1) * 64 + tx];
            ull hp[4];
#pragma unroll
            for (int p = 0; p < 4; p++) PK2(hp[p], h_sh[4 * ty + p][k]);
#pragma unroll
            for (int p = 0; p < 4; p++) {
                FMA2(acc[p][0], hp[p], wa.x, acc[p][0]);
                FMA2(acc[p][1], hp[p], wa.y, acc[p][1]);
                FMA2(acc[p][2], hp[p], wb.x, acc[p][2]);
                FMA2(acc[p][3], hp[p], wb.y, acc[p][3]);
            }
        }
        // input: K = 64
#pragma unroll 4
        for (int k = 0; k < D_IN; k++) {
            ulonglong2 wa = wi2[(k * 2 + 0) * 64 + tx];
            ulonglong2 wb = wi2[(k * 2 + 1) * 64 + tx];
            ull xp[4];
#pragma unroll
            for (int p = 0; p < 4; p++) PK2(xp[p], x_sh[t][4 * ty + p][k]);
#pragma unroll
            for (int p = 0; p < 4; p++) {
                FMA2(acc[p][0], xp[p], wa.x, acc[p][0]);
                FMA2(acc[p][1], xp[p], wa.y, acc[p][1]);
                FMA2(acc[p][2], xp[p], wb.x, acc[p][2]);
                FMA2(acc[p][3], xp[p], wb.y, acc[p][3]);
            }
        }
        __syncthreads();   // all reads of old h done before overwrite
        // epilogue: thread-local i/f/g/o per (ped, channel)
#pragma unroll
        for (int p = 0; p < 4; p++) {
#pragma unroll
            for (int half = 0; half < 2; half++) {
                float iv, fv, gv, ov;
                UNPK2(iv, fv, acc[p][2 * half]);
                UNPK2(gv, ov, acc[p][2 * half + 1]);
                float cn = sigf(fv) * c_reg[p][half] + sigf(iv) * tanh_f(gv);
                c_reg[p][half] = cn;
                h_sh[4 * ty + p][2 * tx + half] = sigf(ov) * tanh_f(cn);
            }
        }
        __syncthreads();   // h visible before next step's reads
    }
    // write h and tanh(h)
    for (int i = tid; i < 16 * H_DIM; i += 256) {
        float v = h_sh[i >> 7][i & 127];
        d_h [(size_t)p0 * H_DIM + i] = v;
        d_th[(size_t)p0 * H_DIM + i] = tanh_f(v);
    }
}

// ---------------- u_h = w_h @ a1, v_h = w_h @ a2 (1 warp per dot) ----------------
__global__ void uv_kernel(const float* __restrict__ gat_w,
                          const float* __restrict__ gat_a)
{
    int w = (blockIdx.x << 2) + (threadIdx.x >> 5);   // 0..1023
    int lane = threadIdx.x & 31;
    int sel = w >> 9;            // 0 = u (a1), 1 = v (a2)
    int h   = (w >> 7) & 3;
    int c   = w & 127;
    const float* a  = gat_a + sel * H_DIM;
    const float* wp = gat_w + ((size_t)h * H_DIM + c) * H_DIM;
    float s = 0.f;
#pragma unroll
    for (int o = lane; o < H_DIM; o += 32) s = fmaf(wp[o], a[o], s);
#pragma unroll
    for (int o = 16; o; o >>= 1) s += __shfl_xor_sync(0xffffffffu, s, o);
    if (lane == 0) d_uv[sel * (NH * H_DIM) + h * H_DIM + c] = s;
}

// ---------------- GAT main: per (group, row i), 128 threads ----------------
__global__ __launch_bounds__(128) void gat_kernel(
    const float* __restrict__ goal_hidden, const float* __restrict__ goal,
    const float* __restrict__ action,      const float* __restrict__ W_dist,
    const float* __restrict__ b_dist,      const float* __restrict__ W_gate,
    const float* __restrict__ b_gate)
{
    int i = blockIdx.x;       // row within group
    int g = blockIdx.y;       // group
    int tid = threadIdx.x;    // 0..127
    int p = g * GRP_N + i;

    __shared__ __align__(16) float th_sh[GRP_N][H_DIM];
    __shared__ __align__(16) float gate_sh[GRP_N][H_DIM];
    __shared__ __align__(16) float r_sh[GRP_N][DD_DIM];
    __shared__ float ahv[H_DIM], ghv[H_DIM];
    __shared__ float pax[GRP_N], pay[GRP_N], pgx[GRP_N], pgy[GRP_N];
    __shared__ float sdot_sh[NH][GRP_N];
    __shared__ float scr[NH][GRP_N + 1];
    __shared__ float alpha_sh[NH][GRP_N + 1];
    __shared__ float hsum[NH][3];

    // P0: loads (tanh precomputed in d_th)
    ahv[tid] = d_h[(size_t)p * H_DIM + tid];
    ghv[tid] = goal_hidden[(size_t)p * H_DIM + tid];
    if (tid < GRP_N) {
        int q = g * GRP_N + tid;
        pax[tid] = action[q * 2 + 0]; pay[tid] = action[q * 2 + 1];
        pgx[tid] = goal[q * 2 + 0];   pgy[tid] = goal[q * 2 + 1];
    }
    for (int j = 0; j < GRP_N; j++)
        th_sh[j][tid] = d_th[(size_t)(g * GRP_N + j) * H_DIM + tid];
    __syncthreads();

    // P1: r[j][d] = relu(dist(i,j) @ W_dist + b_dist)
    {
        float aix = pax[i], aiy = pay[i], gix = pgx[i], giy = pgy[i];
        for (int it = 0; it < 16; it++) {
            int idx = tid + 128 * it;
            int j = idx >> 6, d = idx & 63;
            float acc = b_dist[d];
            acc = fmaf(aix, W_dist[0 * 64 + d], acc);
            acc = fmaf(aiy, W_dist[1 * 64 + d], acc);
            acc = fmaf(gix, W_dist[2 * 64 + d], acc);
            acc = fmaf(giy, W_dist[3 * 64 + d], acc);
            acc = fmaf(pax[j], W_dist[4 * 64 + d], acc);
            acc = fmaf(pay[j], W_dist[5 * 64 + d], acc);
            acc = fmaf(pgx[j], W_dist[6 * 64 + d], acc);
            acc = fmaf(pgy[j], W_dist[7 * 64 + d], acc);
            r_sh[j][d] = fmaxf(acc, 0.f);
        }
    }
    __syncthreads();

    // P2: gate[j][c=tid] = sigmoid(r[j] @ W_gate[:,c] + b_gate[c]) — f32x2
    {
        ull acc2[GRP_N];
#pragma unroll
        for (int j = 0; j < GRP_N; j++) acc2[j] = 0ull;
        for (int d0 = 0; d0 < DD_DIM; d0 += 4) {
            float w0 = W_gate[(d0 + 0) * H_DIM + tid];
            float w1 = W_gate[(d0 + 1) * H_DIM + tid];
            float w2 = W_gate[(d0 + 2) * H_DIM + tid];
            float w3 = W_gate[(d0 + 3) * H_DIM + tid];
            ull ww0, ww1;
            PKAB(ww0, w0, w1);
            PKAB(ww1, w2, w3);
#pragma unroll
            for (int j = 0; j < GRP_N; j++) {
                ulonglong2 rv = *(const ulonglong2*)&r_sh[j][d0];
                FMA2(acc2[j], rv.x, ww0, acc2[j]);
                FMA2(acc2[j], rv.y, ww1, acc2[j]);
            }
        }
        float bg = b_gate[tid];
#pragma unroll
        for (int j = 0; j < GRP_N; j++) {
            float lo, hi;
            UNPK2(lo, hi, acc2[j]);
            gate_sh[j][tid] = sigf(lo + hi + bg);
        }
    }
    __syncthreads();

    // P3: per-head dots (warp h = head h)
    {
        int wid = tid >> 5, lane = tid & 31;
        const float* uh = d_uv + wid * H_DIM;
        const float* vh = d_uv + (NH + wid) * H_DIM;
        for (int j = 0; j < GRP_N; j++) {
            float s = 0.f;
#pragma unroll
            for (int cc = lane; cc < H_DIM; cc += 32)
                s = fmaf(gate_sh[j][cc] * th_sh[j][cc], vh[cc], s);
#pragma unroll
            for (int o = 16; o; o >>= 1) s += __shfl_xor_sync(0xffffffffu, s, o);
            if (lane == 0) sdot_sh[wid][j] = s;
        }
        float su = 0.f, sv = 0.f, sg = 0.f;
#pragma unroll
        for (int cc = lane; cc < H_DIM; cc += 32) {
            su = fmaf(ahv[cc], uh[cc], su);
            sv = fmaf(ahv[cc], vh[cc], sv);
            sg = fmaf(ghv[cc], vh[cc], sg);
        }
#pragma unroll
        for (int o = 16; o; o >>= 1) {
            su += __shfl_xor_sync(0xffffffffu, su, o);
            sv += __shfl_xor_sync(0xffffffffu, sv, o);
            sg += __shfl_xor_sync(0xffffffffu, sg, o);
        }
        if (lane == 0) { hsum[wid][0] = su; hsum[wid][1] = sv; hsum[wid][2] = sg; }
    }
    __syncthreads();

    // P4: leaky-relu scores + softmax over k=0..32 per head
    for (int idx = tid; idx < NH * (GRP_N + 1); idx += 128) {
        int h = idx / (GRP_N + 1), k = idx % (GRP_N + 1);
        float s;
        if (k == 0) s = hsum[h][0] + hsum[h][1];
        else {
            int j = k - 1;
            s = hsum[h][0] + ((j == i) ? hsum[h][2] : sdot_sh[h][j]);
        }
        scr[h][k] = (s >= 0.f) ? s : 0.2f * s;
    }
    __syncthreads();
    if (tid < NH) {
        int h = tid;
        float mx = -1e30f;
        for (int k = 0; k <= GRP_N; k++) mx = fmaxf(mx, scr[h][k]);
        float sum = 0.f;
        for (int k = 0; k <= GRP_N; k++) sum += expf(scr[h][k] - mx);
        float inv = 1.f / sum;
        for (int k = 0; k <= GRP_N; k++) alpha_sh[h][k] = expf(scr[h][k] - mx) * inv;
    }
    __syncthreads();

    // P5: m[h][c] = alpha0*ah[c] + sum_j alpha_{j+1} * goal_action[j][c]
    {
        int c = tid;
        float ahc = ahv[c], ghc = ghv[c];
        for (int h = 0; h < NH; h++) {
            float mv = alpha_sh[h][0] * ahc;
#pragma unroll 8
            for (int j = 0; j < GRP_N; j++) {
                float ga = (j == i) ? ghc : gate_sh[j][c] * th_sh[j][c];
                mv = fmaf(alpha_sh[h][j + 1], ga, mv);
            }
            d_m[((size_t)h * N_PED + p) * H_DIM + c] = mv;
        }
    }
}

// ---------------- final: out = relu(0.25 * sum_h m_h @ w_h) + gat_bias ----------------
__global__ __launch_bounds__(128) void g3_kernel(
    const float* __restrict__ gat_w, const float* __restrict__ gat_bias,
    float* __restrict__ out)
{
    const int TP = 8;
    int p0 = blockIdx.x * TP;
    int tid = threadIdx.x;   // output column c
    __shared__ __align__(16) float m_sh[TP][H_DIM];
    ull acc2[TP];
#pragma unroll
    for (int r = 0; r < TP; r++) acc2[r] = 0ull;

    for (int h = 0; h < NH; h++) {
        __syncthreads();
#pragma unroll
        for (int r = 0; r < TP; r++)
            m_sh[r][tid] = d_m[((size_t)h * N_PED + p0 + r) * H_DIM + tid];
        __syncthreads();
        const float* wh = gat_w + (size_t)h * H_DIM * H_DIM;
        for (int f0 = 0; f0 < H_DIM; f0 += 8) {
            float w0 = wh[(f0 + 0) * H_DIM + tid];
            float w1 = wh[(f0 + 1) * H_DIM + tid];
            float w2 = wh[(f0 + 2) * H_DIM + tid];
            float w3 = wh[(f0 + 3) * H_DIM + tid];
            float w4 = wh[(f0 + 4) * H_DIM + tid];
            float w5 = wh[(f0 + 5) * H_DIM + tid];
            float w6 = wh[(f0 + 6) * H_DIM + tid];
            float w7 = wh[(f0 + 7) * H_DIM + tid];
            ull ww0, ww1, ww2, ww3;
            PKAB(ww0, w0, w1); PKAB(ww1, w2, w3);
            PKAB(ww2, w4, w5); PKAB(ww3, w6, w7);
#pragma unroll
            for (int r = 0; r < TP; r++) {
                ulonglong2 ma = *(const ulonglong2*)&m_sh[r][f0];
                ulonglong2 mb = *(const ulonglong2*)&m_sh[r][f0 + 4];
                FMA2(acc2[r], ma.x, ww0, acc2[r]);
                FMA2(acc2[r], ma.y, ww1, acc2[r]);
                FMA2(acc2[r], mb.x, ww2, acc2[r]);
                FMA2(acc2[r], mb.y, ww3, acc2[r]);
            }
        }
    }
    float b = gat_bias[tid];
#pragma unroll
    for (int r = 0; r < TP; r++) {
        float lo, hi;
        UNPK2(lo, hi, acc2[r]);
        out[(size_t)(p0 + r) * H_DIM + tid] = fmaxf(0.25f * (lo + hi), 0.f) + b;
    }
}

// ---------------- host ----------------
extern "C" void kernel_launch(void* const* d_in, const int* in_sizes, int n_in,
                              void* d_out, int out_size)
{
    const float* obs         = (const float*)d_in[0];
    const float* goal_hidden = (const float*)d_in[1];
    const float* goal        = (const float*)d_in[2];
    const float* action      = (const float*)d_in[3];
    const float* h0          = (const float*)d_in[4];
    const float* c0          = (const float*)d_in[5];
    const float* W_emb       = (const float*)d_in[6];
    const float* b_emb       = (const float*)d_in[7];
    const float* W_ih        = (const float*)d_in[8];
    const float* W_hh        = (const float*)d_in[9];
    const float* b_ih        = (const float*)d_in[10];
    const float* b_hh        = (const float*)d_in[11];
    const float* W_dist      = (const float*)d_in[12];
    const float* b_dist      = (const float*)d_in[13];
    const float* W_gate      = (const float*)d_in[14];
    const float* b_gate      = (const float*)d_in[15];
    const float* gat_w       = (const float*)d_in[16];
    const float* gat_a       = (const float*)d_in[17];
    const float* gat_bias    = (const float*)d_in[18];
    float* out = (float*)d_out;

    // weight prep (permute) + attention-vector fold (independent of LSTM)
    {
        int total = H_DIM * G4H + D_IN * G4H + G4H;
        prep_kernel<<<(total + 255) / 256, 256>>>(W_hh, W_ih, b_ih, b_hh);
    }
    uv_kernel<<<256, 128>>>(gat_w, gat_a);

    // fused embed + 8-step LSTM (writes d_h, d_th)
    lstm_fused<<<N_PED / 16, 256>>>(h0, c0, obs, W_emb, b_emb);

    // GAT
    gat_kernel<<<dim3(GRP_N, N_GRP), 128>>>(goal_hidden, goal, action,
                                            W_dist, b_dist, W_gate, b_gate);
    g3_kernel<<<N_PED / 8, 128>>>(gat_w, gat_bias, out);
}